// round 15
// baseline (speedup 1.0000x reference)
#include <cuda_runtime.h>
#include <cuda_bf16.h>
#include <math.h>

#define BB      4                 // batch
#define KH      18                // harmonics
#define TPB     128               // points per tile == threads per block
#define STAGES  3
#define TILE_F  (TPB * KH)        // 2304 floats per array per tile
#define TILE_F4 (TILE_F / 4)      // 576 float4

__device__ __forceinline__ void cp_async16(void* smem, const void* gmem) {
    unsigned s = (unsigned)__cvta_generic_to_shared(smem);
    asm volatile("cp.async.cg.shared.global [%0], [%1], 16;\n" :: "r"(s), "l"(gmem));
}
#define CP_COMMIT() asm volatile("cp.async.commit_group;\n" ::: "memory")
#define CP_WAIT1()  asm volatile("cp.async.wait_group 1;\n" ::: "memory")

// Self-restoring work-stealing state: the LAST block to finish resets both
// counters, so every launch / graph replay starts from identical state with
// no separate reset kernel node.
__device__ int g_tile_ctr = 0;
__device__ int g_done_ctr = 0;

template <bool FULL>   // FULL: every tile is complete (N % TPB == 0)
__global__ __launch_bounds__(TPB) void dddm_kernel(
    const float* __restrict__ t_in,
    const float* __restrict__ poly,
    const float* __restrict__ fa,
    const float* __restrict__ fb,
    const int*   __restrict__ stage_p,
    float*       __restrict__ out,
    int N, int ntiles)
{
    __shared__ float  sA[STAGES][TILE_F];   // fa tiles  (27.6 KB)
    __shared__ float  sB[STAGES][TILE_F];   // fb tiles  (27.6 KB)
    __shared__ float2 tbl[BB][KH];          // (cos,sin); zeroed if band inactive
    __shared__ float  tsh[BB];
    __shared__ int    s_first[2];           // prologue broadcast (t_cur, t_nxt)
    __shared__ int    s_pend[2];            // pipelined steal slots
    // total ~55.9 KB -> 4 blocks/SM

    const int tid = threadIdx.x;

    // ---- trig table: once per block (amortized over ~28 tiles) ----
    if (tid < BB * KH) {
        const int b = tid / KH;
        const int k = tid % KH;
        float t = t_in[b];
        if (k == 0) tsh[b] = t;
        int st = stage_p ? stage_p[0] : 3;
        int cs = (st < 0) ? 3 : (st > 3 ? 3 : st);
        int req = (k < 3) ? 1 : ((k < 9) ? 2 : 3);
        float x = (float)(k + 1) * t;       // fold (k+1)t into [0,1) for accuracy
        x -= floorf(x);
        float s, c;
        sincosf(6.28318530717958647692f * x, &s, &c);
        bool act = (cs >= req);
        tbl[b][k] = make_float2(act ? c : 0.0f, act ? s : 0.0f);
    }

    // ---- async prefetch of one full fourier tile into a stage ----
    auto prefetch = [&](int stg, int tile) {
        if (tile < ntiles && (FULL || (tile + 1) * TPB <= N)) {
            const float4* __restrict__ ga4 = (const float4*)fa + (size_t)tile * TILE_F4;
            const float4* __restrict__ gb4 = (const float4*)fb + (size_t)tile * TILE_F4;
            float4* __restrict__ da4 = (float4*)sA[stg];
            float4* __restrict__ db4 = (float4*)sB[stg];
            #pragma unroll
            for (int i = tid; i < TILE_F4; i += TPB) {  // 4 full + 1 half pass
                cp_async16(&da4[i], &ga4[i]);
                cp_async16(&db4[i], &gb4[i]);
            }
        }
    };

    // ---- prologue: steal three tiles (t_cur, t_nxt, pending for iter 0) ----
    if (tid == 0) {
        int a = atomicAdd(&g_tile_ctr, 3);
        s_first[0] = a;
        s_first[1] = a + 1;
        s_pend[0]  = a + 2;
    }
    __syncthreads();                 // also publishes the trig table
    int t_cur = s_first[0];
    int t_nxt = s_first[1];

    prefetch(0, t_cur);   CP_COMMIT();
    prefetch(1, t_nxt);   CP_COMMIT();

    // poly software-prefetch (registers, no smem): row for t_cur in flight now
    float4 pc_next = make_float4(0.f, 0.f, 0.f, 0.f);
    if (t_cur < ntiles && (size_t)t_cur * TPB + tid < (size_t)N)
        pc_next = *((const float4*)poly + (size_t)t_cur * TPB + tid);

    int s0 = 0, s1 = 1, s2 = 2;      // ring indices (rotate; no modulo)
    int slot = 0;                    // pending-steal slot for this iteration
    while (t_cur < ntiles) {
        CP_WAIT1();            // t_cur's group complete (t_nxt still in flight)
        __syncthreads();       // cp.asyncs visible; s_pend[slot] (written last
                               // iter) published; prev iter's readers done
        const int t_new = s_pend[slot];

        // issue NEXT iteration's steal now: ~300cy ATOMG latency overlaps the
        // whole compute phase instead of sitting inside the barrier window
        if (tid == 0) s_pend[slot ^ 1] = atomicAdd(&g_tile_ctr, 1);
        slot ^= 1;

        prefetch(s2, t_new);   // into the stage just freed by the barrier
        CP_COMMIT();           // exactly one commit per iteration

        const int n = t_cur * TPB + tid;

        float4 pc = pc_next;   // consume in-flight poly row for t_cur
        if (t_nxt < ntiles) {  // issue t_nxt's poly LDG; hides under compute
            const size_t nn = (size_t)t_nxt * TPB + tid;
            if (nn < (size_t)N)
                pc_next = *((const float4*)poly + nn);
        }

        if (FULL || n < N) {
            float accp[BB], accf[BB];
            #pragma unroll
            for (int b = 0; b < BB; ++b) {
                float t = tsh[b];
                accp[b] = fmaf(fmaf(fmaf(pc.w, t, pc.z), t, pc.y), t, pc.x);
                accf[b] = 0.0f;
            }

            // lane row at tid*18 floats: float2-aligned; stride 18 floats
            // -> 16 distinct banks per 16-lane phase: conflict-free LDS.64
            const bool infull = FULL || ((t_cur + 1) * TPB <= N);
            const float2* __restrict__ rowA = infull
                ? (const float2*)(sA[s0] + tid * KH)
                : (const float2*)(fa + (size_t)n * KH);
            const float2* __restrict__ rowB = infull
                ? (const float2*)(sB[s0] + tid * KH)
                : (const float2*)(fb + (size_t)n * KH);

            #pragma unroll
            for (int kk = 0; kk < KH / 2; ++kk) {
                float2 a2 = rowA[kk];
                float2 b2 = rowB[kk];
                #pragma unroll
                for (int b = 0; b < BB; ++b) {
                    // (c0,s0,c1,s1) harmonics 2kk,2kk+1 — LDS.128 broadcast
                    float4 w = ((const float4*)(&tbl[b][0]))[kk];
                    accf[b] = fmaf(a2.x, w.x, accf[b]);
                    accf[b] = fmaf(b2.x, w.y, accf[b]);
                    accf[b] = fmaf(a2.y, w.z, accf[b]);
                    accf[b] = fmaf(b2.y, w.w, accf[b]);
                }
            }

            // streaming stores: touch-once, evict-first, keep L2 for reads
            const size_t NN = (size_t)N;
            #pragma unroll
            for (int b = 0; b < BB; ++b) {
                __stcs(out + (size_t)b * NN + n, accp[b]);          // y_poly
                __stcs(out + (size_t)(BB + b) * NN + n, accf[b]);   // y_fourier
            }
        }

        t_cur = t_nxt;
        t_nxt = t_new;
        int tmp = s0; s0 = s1; s1 = s2; s2 = tmp;   // rotate ring
    }

    // ---- epilogue: last block to finish restores the stealing state ----
    // Every block's final g_tile_ctr atomic strictly precedes its arrival
    // here, so when the last block arrives no further steals can occur and
    // the reset races with nothing. Leaves both counters 0 for next launch.
    if (tid == 0) {
        __threadfence();
        int d = atomicAdd(&g_done_ctr, 1);
        if (d == (int)gridDim.x - 1) {
            g_tile_ctr = 0;
            g_done_ctr = 0;
            __threadfence();
        }
    }
}

extern "C" void kernel_launch(void* const* d_in, const int* in_sizes, int n_in,
                              void* d_out, int out_size)
{
    const float* t_in  = (const float*)d_in[0];
    const float* poly  = (const float*)d_in[1];
    const float* fa    = (const float*)d_in[2];
    const float* fb    = (const float*)d_in[3];
    const int*   stage = (n_in > 4) ? (const int*)d_in[4] : nullptr;

    const int N = in_sizes[1] / 4;                 // poly_coeffs is [N, 4]
    float* outp = (float*)d_out;

    const int ntiles = (N + TPB - 1) / TPB;        // 16384 for 128^3
    int grid = 148 * 4;                            // one resident wave @4 blk/SM
    if (grid > ntiles) grid = ntiles;

    if (N % TPB == 0)
        dddm_kernel<true><<<grid, TPB>>>(t_in, poly, fa, fb, stage, outp, N, ntiles);
    else
        dddm_kernel<false><<<grid, TPB>>>(t_in, poly, fa, fb, stage, outp, N, ntiles);
}